// round 1
// baseline (speedup 1.0000x reference)
#include <cuda_runtime.h>
#include <math.h>

#define NB 4
#define NC 128
#define NHW 4096

// ---- scratch (no cudaMalloc allowed) ----
__device__ float g_q[NB * NC * NHW];
__device__ float g_k[NB * NC * NHW];
__device__ float g_v[NB * NC * NHW];
__device__ float g_attn[(size_t)NB * NHW * NHW];   // 256 MiB

// ============================================================
// Kernel 1: 1x1 conv (channel matmul) + BN + ELU
//   out[b,o,hw] = elu( (sum_c w[o,c] x[b,c,hw] + cb[o]) * inv_o + add_o )
// grid (HW/64, B), block 256.  Tile: 128 o x 64 hw, K=128 in chunks of 32.
// ============================================================
__global__ __launch_bounds__(256, 2) void proj_kernel(
    const float* __restrict__ x, const float* __restrict__ w,
    const float* __restrict__ cb, const float* __restrict__ bns,
    const float* __restrict__ bnb, const float* __restrict__ bnm,
    const float* __restrict__ bnv, int which)
{
    __shared__ float xs[NC][64];
    __shared__ float ws[32][NC];

    float* out = (which == 0) ? g_q : (which == 1) ? g_k : g_v;

    const int b   = blockIdx.y;
    const int hw0 = blockIdx.x * 64;
    const int tid = threadIdx.x;
    const int tx  = tid & 15;   // hw group (4 each)
    const int ty  = tid >> 4;   // o group (8 each)
    const float* xb = x + (size_t)b * NC * NHW;

    // load x tile [128c][64hw]
    for (int i = tid; i < NC * 16; i += 256) {
        int c = i >> 4, j = (i & 15) << 2;
        *(float4*)&xs[c][j] = *(const float4*)&xb[(size_t)c * NHW + hw0 + j];
    }

    float acc[8][4];
#pragma unroll
    for (int i = 0; i < 8; i++)
#pragma unroll
        for (int j = 0; j < 4; j++) acc[i][j] = 0.f;

    for (int c0 = 0; c0 < NC; c0 += 32) {
        __syncthreads();
        // ws[cc][o] = w[o][c0+cc]   (transpose for broadcast reads)
        for (int i = tid; i < 1024; i += 256) {
            int o = i >> 3, cf = (i & 7) << 2;
            float4 t = *(const float4*)&w[o * NC + c0 + cf];
            ws[cf + 0][o] = t.x; ws[cf + 1][o] = t.y;
            ws[cf + 2][o] = t.z; ws[cf + 3][o] = t.w;
        }
        __syncthreads();
#pragma unroll 4
        for (int cc = 0; cc < 32; cc++) {
            float wr[8];
            *(float4*)&wr[0] = *(float4*)&ws[cc][ty * 8];
            *(float4*)&wr[4] = *(float4*)&ws[cc][ty * 8 + 4];
            float4 xv = *(float4*)&xs[c0 + cc][tx * 4];
#pragma unroll
            for (int i = 0; i < 8; i++) {
                acc[i][0] += wr[i] * xv.x;
                acc[i][1] += wr[i] * xv.y;
                acc[i][2] += wr[i] * xv.z;
                acc[i][3] += wr[i] * xv.w;
            }
        }
    }

#pragma unroll
    for (int i = 0; i < 8; i++) {
        int o = ty * 8 + i;
        float inv = bns[o] * rsqrtf(bnv[o] + 1e-5f);
        float add = cb[o] * inv + bnb[o] - bnm[o] * inv;
        float4 r;
        float v0 = acc[i][0] * inv + add; r.x = v0 > 0.f ? v0 : expm1f(v0);
        float v1 = acc[i][1] * inv + add; r.y = v1 > 0.f ? v1 : expm1f(v1);
        float v2 = acc[i][2] * inv + add; r.z = v2 > 0.f ? v2 : expm1f(v2);
        float v3 = acc[i][3] * inv + add; r.w = v3 > 0.f ? v3 : expm1f(v3);
        *(float4*)&out[(size_t)(b * NC + o) * NHW + hw0 + tx * 4] = r;
    }
}

// ============================================================
// Kernel 2: energy[b,qi,ki] = sum_c q[b,c,qi] * k[b,c,ki]
// grid (32,32,B), block 256. Tile 128x128, K=128 in chunks of 32.
// Conflict-free split micro-tile: cols {tx*4, 64+tx*4}, rows {ty*4, 64+ty*4}
// ============================================================
__global__ __launch_bounds__(256, 2) void energy_kernel()
{
    __shared__ float qs[32][128];
    __shared__ float ks[32][128];

    const int b  = blockIdx.z;
    const int q0 = blockIdx.y << 7;
    const int k0 = blockIdx.x << 7;
    const int tid = threadIdx.x;
    const int tx = tid & 15, ty = tid >> 4;
    const float* qb = g_q + (size_t)b * NC * NHW;
    const float* kb = g_k + (size_t)b * NC * NHW;

    float acc[8][8];
#pragma unroll
    for (int i = 0; i < 8; i++)
#pragma unroll
        for (int j = 0; j < 8; j++) acc[i][j] = 0.f;

    for (int c0 = 0; c0 < NC; c0 += 32) {
        __syncthreads();
        for (int i = tid; i < 1024; i += 256) {
            int c = i >> 5, f = (i & 31) << 2;
            *(float4*)&qs[c][f] = *(const float4*)&qb[(size_t)(c0 + c) * NHW + q0 + f];
            *(float4*)&ks[c][f] = *(const float4*)&kb[(size_t)(c0 + c) * NHW + k0 + f];
        }
        __syncthreads();
#pragma unroll 8
        for (int c = 0; c < 32; c++) {
            float4 a0 = *(float4*)&qs[c][ty * 4];
            float4 a1 = *(float4*)&qs[c][64 + ty * 4];
            float4 b0 = *(float4*)&ks[c][tx * 4];
            float4 b1 = *(float4*)&ks[c][64 + tx * 4];
            float ar[8] = {a0.x, a0.y, a0.z, a0.w, a1.x, a1.y, a1.z, a1.w};
            float br[8] = {b0.x, b0.y, b0.z, b0.w, b1.x, b1.y, b1.z, b1.w};
#pragma unroll
            for (int i = 0; i < 8; i++)
#pragma unroll
                for (int j = 0; j < 8; j++) acc[i][j] += ar[i] * br[j];
        }
    }

    float* arow = g_attn + (size_t)b * NHW * NHW;
#pragma unroll
    for (int i = 0; i < 8; i++) {
        int qi = q0 + ((i < 4) ? ty * 4 + i : 64 + ty * 4 + (i - 4));
        float4 r0 = make_float4(acc[i][0], acc[i][1], acc[i][2], acc[i][3]);
        float4 r1 = make_float4(acc[i][4], acc[i][5], acc[i][6], acc[i][7]);
        *(float4*)&arow[(size_t)qi * NHW + k0 + tx * 4]      = r0;
        *(float4*)&arow[(size_t)qi * NHW + k0 + 64 + tx * 4] = r1;
    }
}

// ============================================================
// Kernel 3: row softmax over last axis, in place. Row register-resident.
// grid (HW, B), block 256 (16 floats/thread).
// ============================================================
__global__ __launch_bounds__(256) void softmax_kernel()
{
    __shared__ float sbuf[8];
    const int b = blockIdx.y;
    const int q = blockIdx.x;
    float* row = g_attn + (size_t)b * NHW * NHW + (size_t)q * NHW;
    const int tid = threadIdx.x;

    float4 r[4];
#pragma unroll
    for (int j = 0; j < 4; j++) r[j] = *(float4*)&row[(tid + j * 256) * 4];

    float m = r[0].x;
#pragma unroll
    for (int j = 0; j < 4; j++) {
        m = fmaxf(m, fmaxf(fmaxf(r[j].x, r[j].y), fmaxf(r[j].z, r[j].w)));
    }
#pragma unroll
    for (int o = 16; o > 0; o >>= 1) m = fmaxf(m, __shfl_xor_sync(0xffffffffu, m, o));
    if ((tid & 31) == 0) sbuf[tid >> 5] = m;
    __syncthreads();
    m = sbuf[0];
#pragma unroll
    for (int w = 1; w < 8; w++) m = fmaxf(m, sbuf[w]);
    __syncthreads();

    float s = 0.f;
#pragma unroll
    for (int j = 0; j < 4; j++) {
        r[j].x = expf(r[j].x - m); s += r[j].x;
        r[j].y = expf(r[j].y - m); s += r[j].y;
        r[j].z = expf(r[j].z - m); s += r[j].z;
        r[j].w = expf(r[j].w - m); s += r[j].w;
    }
#pragma unroll
    for (int o = 16; o > 0; o >>= 1) s += __shfl_xor_sync(0xffffffffu, s, o);
    if ((tid & 31) == 0) sbuf[tid >> 5] = s;
    __syncthreads();
    s = 0.f;
#pragma unroll
    for (int w = 0; w < 8; w++) s += sbuf[w];
    float inv = 1.f / s;

#pragma unroll
    for (int j = 0; j < 4; j++) {
        r[j].x *= inv; r[j].y *= inv; r[j].z *= inv; r[j].w *= inv;
        *(float4*)&row[(tid + j * 256) * 4] = r[j];
    }
}

// ============================================================
// Kernel 4: out[b,c,qi] = gamma * sum_k v[b,c,k]*attn[b,qi,k] + beta * x_v[b,c,qi]
// grid (32, B), block 256. Tile 128c x 128qi, K=4096 in chunks of 32.
// Both operands K-contiguous in gmem -> transpose into k-major smem tiles.
// ============================================================
__global__ __launch_bounds__(256, 2) void out_kernel(
    const float* __restrict__ xv, const float* __restrict__ gamma,
    const float* __restrict__ beta, float* __restrict__ out)
{
    __shared__ float vs[32][132];
    __shared__ float as[32][132];

    const int b  = blockIdx.y;
    const int q0 = blockIdx.x << 7;
    const int tid = threadIdx.x;
    const int tx = tid & 15, ty = tid >> 4;   // tx -> qi, ty -> c
    const float* vb = g_v + (size_t)b * NC * NHW;
    const float* ab = g_attn + (size_t)b * NHW * NHW;

    float acc[8][8];
#pragma unroll
    for (int i = 0; i < 8; i++)
#pragma unroll
        for (int j = 0; j < 8; j++) acc[i][j] = 0.f;

    for (int k0 = 0; k0 < NHW; k0 += 32) {
        __syncthreads();
        for (int i = tid; i < 1024; i += 256) {
            int r = i >> 3, kf = (i & 7) << 2;
            float4 t = *(const float4*)&vb[(size_t)r * NHW + k0 + kf];
            vs[kf + 0][r] = t.x; vs[kf + 1][r] = t.y;
            vs[kf + 2][r] = t.z; vs[kf + 3][r] = t.w;
            float4 u = *(const float4*)&ab[(size_t)(q0 + r) * NHW + k0 + kf];
            as[kf + 0][r] = u.x; as[kf + 1][r] = u.y;
            as[kf + 2][r] = u.z; as[kf + 3][r] = u.w;
        }
        __syncthreads();
#pragma unroll 8
        for (int k = 0; k < 32; k++) {
            float4 c0v = *(float4*)&vs[k][ty * 4];
            float4 c1v = *(float4*)&vs[k][64 + ty * 4];
            float4 p0  = *(float4*)&as[k][tx * 4];
            float4 p1  = *(float4*)&as[k][64 + tx * 4];
            float cr[8] = {c0v.x, c0v.y, c0v.z, c0v.w, c1v.x, c1v.y, c1v.z, c1v.w};
            float pr[8] = {p0.x, p0.y, p0.z, p0.w, p1.x, p1.y, p1.z, p1.w};
#pragma unroll
            for (int i = 0; i < 8; i++)
#pragma unroll
                for (int j = 0; j < 8; j++) acc[i][j] += cr[i] * pr[j];
        }
    }

    const float g  = gamma[0];
    const float be = beta[0];
#pragma unroll
    for (int i = 0; i < 8; i++) {
        int c = (i < 4) ? ty * 4 + i : 64 + ty * 4 + (i - 4);
        const float* xrow = xv + (size_t)(b * NC + c) * NHW;
        float* orow = out + (size_t)(b * NC + c) * NHW;

        int col0 = q0 + tx * 4;
        float4 xv0 = *(const float4*)&xrow[col0];
        float4 r0;
        r0.x = g * acc[i][0] + be * xv0.x;
        r0.y = g * acc[i][1] + be * xv0.y;
        r0.z = g * acc[i][2] + be * xv0.z;
        r0.w = g * acc[i][3] + be * xv0.w;
        *(float4*)&orow[col0] = r0;

        int col1 = q0 + 64 + tx * 4;
        float4 xv1 = *(const float4*)&xrow[col1];
        float4 r1;
        r1.x = g * acc[i][4] + be * xv1.x;
        r1.y = g * acc[i][5] + be * xv1.y;
        r1.z = g * acc[i][6] + be * xv1.z;
        r1.w = g * acc[i][7] + be * xv1.w;
        *(float4*)&orow[col1] = r1;
    }
}

// ============================================================
extern "C" void kernel_launch(void* const* d_in, const int* in_sizes, int n_in,
                              void* d_out, int out_size)
{
    const float* x_q = (const float*)d_in[0];
    const float* x_k = (const float*)d_in[1];
    const float* x_v = (const float*)d_in[2];

    const float* q_w = (const float*)d_in[3];
    const float* q_b = (const float*)d_in[4];
    const float* q_s = (const float*)d_in[5];
    const float* q_bb = (const float*)d_in[6];
    const float* q_m = (const float*)d_in[7];
    const float* q_v = (const float*)d_in[8];

    const float* k_w = (const float*)d_in[9];
    const float* k_b = (const float*)d_in[10];
    const float* k_s = (const float*)d_in[11];
    const float* k_bb = (const float*)d_in[12];
    const float* k_m = (const float*)d_in[13];
    const float* k_v = (const float*)d_in[14];

    const float* v_w = (const float*)d_in[15];
    const float* v_b = (const float*)d_in[16];
    const float* v_s = (const float*)d_in[17];
    const float* v_bb = (const float*)d_in[18];
    const float* v_m = (const float*)d_in[19];
    const float* v_v = (const float*)d_in[20];

    const float* gamma = (const float*)d_in[21];
    const float* beta  = (const float*)d_in[22];

    dim3 bp(NHW / 64, NB);
    proj_kernel<<<bp, 256>>>(x_q, q_w, q_b, q_s, q_bb, q_m, q_v, 0);
    proj_kernel<<<bp, 256>>>(x_k, k_w, k_b, k_s, k_bb, k_m, k_v, 1);
    proj_kernel<<<bp, 256>>>(x_v, v_w, v_b, v_s, v_bb, v_m, v_v, 2);

    dim3 ge(NHW / 128, NHW / 128, NB);
    energy_kernel<<<ge, 256>>>();

    dim3 gs(NHW, NB);
    softmax_kernel<<<gs, 256>>>();

    dim3 go(NHW / 128, NB);
    out_kernel<<<go, 256>>>(x_v, gamma, beta, (float*)d_out);
}

// round 7
// speedup vs baseline: 2.7153x; 2.7153x over previous
#include <cuda_runtime.h>
#include <cuda_bf16.h>
#include <cstdint>
#include <math.h>

#define NB 4
#define NC 128
#define NHW 4096

// ---- scratch (no cudaMalloc; ~280 MiB total) ----
__device__ __nv_bfloat16 g_qh[(size_t)NB * NHW * NC];   // [b][hw][c]
__device__ __nv_bfloat16 g_ql[(size_t)NB * NHW * NC];
__device__ __nv_bfloat16 g_kh[(size_t)NB * NHW * NC];
__device__ __nv_bfloat16 g_kl[(size_t)NB * NHW * NC];
__device__ __nv_bfloat16 g_vh[(size_t)NB * NC * NHW];   // [b][c][hw]
__device__ __nv_bfloat16 g_vl[(size_t)NB * NC * NHW];
__device__ __nv_bfloat16 g_ah[(size_t)NB * NHW * NHW];  // [b][q][k] energies -> probs (hi)
__device__ __nv_bfloat16 g_al[(size_t)NB * NHW * NHW];  // (lo)

// ============================================================
// helpers (family-portable PTX only: ldmatrix sm_75+, mma.sync sm_80+)
// ============================================================
__device__ __forceinline__ uint32_t smem_to_u32(const void* p) {
    uint32_t a;
    asm("{ .reg .u64 t; cvta.to.shared.u64 t, %1; cvt.u32.u64 %0, t; }" : "=r"(a) : "l"(p));
    return a;
}
__device__ __forceinline__ void ldsm_x4(uint32_t* r, uint32_t addr) {
    asm volatile("ldmatrix.sync.aligned.m8n8.x4.shared.b16 {%0,%1,%2,%3}, [%4];"
                 : "=r"(r[0]), "=r"(r[1]), "=r"(r[2]), "=r"(r[3]) : "r"(addr));
}
__device__ __forceinline__ void mma16816(float* c, const uint32_t* a, const uint32_t* b) {
    asm volatile("mma.sync.aligned.m16n8k16.row.col.f32.bf16.bf16.f32 "
                 "{%0,%1,%2,%3}, {%4,%5,%6,%7}, {%8,%9}, {%0,%1,%2,%3};"
                 : "+f"(c[0]), "+f"(c[1]), "+f"(c[2]), "+f"(c[3])
                 : "r"(a[0]), "r"(a[1]), "r"(a[2]), "r"(a[3]), "r"(b[0]), "r"(b[1]));
}
__device__ __forceinline__ void split_bf16(float v, __nv_bfloat16& h, __nv_bfloat16& l) {
    h = __float2bfloat16_rn(v);
    l = __float2bfloat16_rn(v - __bfloat162float(h));
}
__device__ __forceinline__ uint32_t pack2(__nv_bfloat16 a, __nv_bfloat16 b) {
    __nv_bfloat162 t(a, b);
    return *(uint32_t*)&t;
}

// tile geometry: 128 rows x 32 bf16 per chunk, row padded 64B -> 80B.
// ldmatrix 16B-bank index = (5r + ch) mod 8 : distinct over any 8 rows.
#define T_ROWB 80
#define T_BYTES (128 * T_ROWB)   // 10240; 4 tiles = 40960 B static smem

// ============================================================
// Kernel 1: 1x1 conv + BN + ELU, writes bf16 hi/lo split.
//   which 0/1 (q/k): layout [b][hw][c]; which 2 (v): [b][c][hw]
// grid (HW/64, B), block 256
// ============================================================
__global__ __launch_bounds__(256, 2) void proj_kernel(
    const float* __restrict__ x, const float* __restrict__ w,
    const float* __restrict__ cb, const float* __restrict__ bns,
    const float* __restrict__ bnb, const float* __restrict__ bnm,
    const float* __restrict__ bnv, int which)
{
    __shared__ float xs[NC][64];
    __shared__ float ws[32][NC];

    __nv_bfloat16* dh = (which == 0) ? g_qh : (which == 1) ? g_kh : g_vh;
    __nv_bfloat16* dl = (which == 0) ? g_ql : (which == 1) ? g_kl : g_vl;

    const int b   = blockIdx.y;
    const int hw0 = blockIdx.x * 64;
    const int tid = threadIdx.x;
    const int tx  = tid & 15;
    const int ty  = tid >> 4;
    const float* xb = x + (size_t)b * NC * NHW;

    for (int i = tid; i < NC * 16; i += 256) {
        int c = i >> 4, j = (i & 15) << 2;
        *(float4*)&xs[c][j] = *(const float4*)&xb[(size_t)c * NHW + hw0 + j];
    }

    float acc[8][4];
#pragma unroll
    for (int i = 0; i < 8; i++)
#pragma unroll
        for (int j = 0; j < 4; j++) acc[i][j] = 0.f;

    for (int c0 = 0; c0 < NC; c0 += 32) {
        __syncthreads();
        for (int i = tid; i < 1024; i += 256) {
            int o = i >> 3, cf = (i & 7) << 2;
            float4 t = *(const float4*)&w[o * NC + c0 + cf];
            ws[cf + 0][o] = t.x; ws[cf + 1][o] = t.y;
            ws[cf + 2][o] = t.z; ws[cf + 3][o] = t.w;
        }
        __syncthreads();
#pragma unroll 4
        for (int cc = 0; cc < 32; cc++) {
            float wr[8];
            *(float4*)&wr[0] = *(float4*)&ws[cc][ty * 8];
            *(float4*)&wr[4] = *(float4*)&ws[cc][ty * 8 + 4];
            float4 xv = *(float4*)&xs[c0 + cc][tx * 4];
#pragma unroll
            for (int i = 0; i < 8; i++) {
                acc[i][0] += wr[i] * xv.x;
                acc[i][1] += wr[i] * xv.y;
                acc[i][2] += wr[i] * xv.z;
                acc[i][3] += wr[i] * xv.w;
            }
        }
    }

    float vout[8][4];
#pragma unroll
    for (int i = 0; i < 8; i++) {
        int o = ty * 8 + i;
        float inv = bns[o] * rsqrtf(bnv[o] + 1e-5f);
        float add = cb[o] * inv + bnb[o] - bnm[o] * inv;
#pragma unroll
        for (int j = 0; j < 4; j++) {
            float v = acc[i][j] * inv + add;
            vout[i][j] = v > 0.f ? v : expm1f(v);
        }
    }

    if (which < 2) {
#pragma unroll
        for (int j = 0; j < 4; j++) {
            int hw = hw0 + tx * 4 + j;
            __nv_bfloat16 h8[8], l8[8];
#pragma unroll
            for (int i = 0; i < 8; i++) split_bf16(vout[i][j], h8[i], l8[i]);
            size_t off = ((size_t)b * NHW + hw) * NC + ty * 8;
            *(uint4*)&dh[off] = *(uint4*)h8;
            *(uint4*)&dl[off] = *(uint4*)l8;
        }
    } else {
#pragma unroll
        for (int i = 0; i < 8; i++) {
            int o = ty * 8 + i;
            __nv_bfloat16 h4[4], l4[4];
#pragma unroll
            for (int j = 0; j < 4; j++) split_bf16(vout[i][j], h4[j], l4[j]);
            size_t off = ((size_t)(b * NC + o)) * NHW + hw0 + tx * 4;
            *(uint2*)&dh[off] = *(uint2*)h4;
            *(uint2*)&dl[off] = *(uint2*)l4;
        }
    }
}

// ============================================================
// Kernel 2: energy[b,qi,ki] = sum_c q.k  (bf16x3 mma.sync)
// grid (32,32,B), block 256 (8 warps, 2x4). K=128 in 4 chunks of 32.
// Writes energies as bf16 hi/lo into g_ah/g_al (softmax renormalizes in place).
// ============================================================
__global__ __launch_bounds__(256, 1) void energy_tc_kernel()
{
    __shared__ __align__(16) char st[4][T_BYTES];   // qh, ql, kh, kl
    const int tid = threadIdx.x, wid = tid >> 5, lane = tid & 31;
    const int b = blockIdx.z, q0 = blockIdx.y << 7, k0 = blockIdx.x << 7;

    const char* srcs[4] = {
        (const char*)(g_qh + ((size_t)b * NHW + q0) * NC),
        (const char*)(g_ql + ((size_t)b * NHW + q0) * NC),
        (const char*)(g_kh + ((size_t)b * NHW + k0) * NC),
        (const char*)(g_kl + ((size_t)b * NHW + k0) * NC) };

    uint4 pf[4][2];
    auto fetch = [&](int kc) {
#pragma unroll
        for (int t = 0; t < 4; t++)
#pragma unroll
            for (int j = 0; j < 2; j++) {
                int idx = j * 256 + tid, r = idx >> 2, ch = idx & 3;
                pf[t][j] = *(const uint4*)(srcs[t] + (size_t)r * 256 + kc * 64 + ch * 16);
            }
    };
    auto stos = [&]() {
#pragma unroll
        for (int t = 0; t < 4; t++)
#pragma unroll
            for (int j = 0; j < 2; j++) {
                int idx = j * 256 + tid, r = idx >> 2, ch = idx & 3;
                *(uint4*)(st[t] + r * T_ROWB + ch * 16) = pf[t][j];
            }
    };

    const int wm = wid & 1, wn = wid >> 1;
    const int lrA = lane & 15, lcA = lane >> 4;

    float acc[4][4][4];
#pragma unroll
    for (int am = 0; am < 4; am++)
#pragma unroll
        for (int an = 0; an < 4; an++)
#pragma unroll
            for (int f = 0; f < 4; f++) acc[am][an][f] = 0.f;

    const uint32_t tqh = smem_to_u32(st[0]), tql = smem_to_u32(st[1]);
    const uint32_t tkh = smem_to_u32(st[2]), tkl = smem_to_u32(st[3]);

    fetch(0); stos();
    __syncthreads();

    for (int kc = 0; kc < 4; kc++) {
        if (kc < 3) fetch(kc + 1);
#pragma unroll
        for (int kk = 0; kk < 2; kk++) {
            int chl = kk * 2 + lcA;
            uint32_t ah[4][4], al[4][4];
#pragma unroll
            for (int am = 0; am < 4; am++) {
                uint32_t off = (uint32_t)((wm * 64 + am * 16 + lrA) * T_ROWB + chl * 16);
                ldsm_x4(ah[am], tqh + off);
                ldsm_x4(al[am], tql + off);
            }
            uint32_t bh[4][2], bl[4][2];
#pragma unroll
            for (int pr = 0; pr < 2; pr++) {
                uint32_t off = (uint32_t)((wn * 32 + pr * 16 + lrA) * T_ROWB + chl * 16);
                uint32_t t[4];
                ldsm_x4(t, tkh + off);
                bh[pr * 2][0] = t[0]; bh[pr * 2][1] = t[2];
                bh[pr * 2 + 1][0] = t[1]; bh[pr * 2 + 1][1] = t[3];
                ldsm_x4(t, tkl + off);
                bl[pr * 2][0] = t[0]; bl[pr * 2][1] = t[2];
                bl[pr * 2 + 1][0] = t[1]; bl[pr * 2 + 1][1] = t[3];
            }
#pragma unroll
            for (int am = 0; am < 4; am++)
#pragma unroll
                for (int an = 0; an < 4; an++) {
                    mma16816(acc[am][an], ah[am], bh[an]);
                    mma16816(acc[am][an], ah[am], bl[an]);
                    mma16816(acc[am][an], al[am], bh[an]);
                }
        }
        __syncthreads();
        if (kc < 3) { stos(); __syncthreads(); }
    }

    // epilogue: split energies to bf16 hi/lo
    const int g = lane >> 2, i2 = (lane & 3) << 1;
#pragma unroll
    for (int am = 0; am < 4; am++)
#pragma unroll
        for (int an = 0; an < 4; an++) {
            int row = q0 + wm * 64 + am * 16 + g;
            int col = k0 + wn * 32 + an * 8 + i2;
            size_t off = ((size_t)b * NHW + row) * NHW + col;
            __nv_bfloat16 h0, l0, h1, l1;
            split_bf16(acc[am][an][0], h0, l0);
            split_bf16(acc[am][an][1], h1, l1);
            *(uint32_t*)&g_ah[off] = pack2(h0, h1);
            *(uint32_t*)&g_al[off] = pack2(l0, l1);
            size_t off8 = off + (size_t)8 * NHW;
            split_bf16(acc[am][an][2], h0, l0);
            split_bf16(acc[am][an][3], h1, l1);
            *(uint32_t*)&g_ah[off8] = pack2(h0, h1);
            *(uint32_t*)&g_al[off8] = pack2(l0, l1);
        }
}

// ============================================================
// Kernel 3: softmax in place on (g_ah + g_al). grid (HW, B), 256 thr.
// ============================================================
__global__ __launch_bounds__(256) void softmax_kernel()
{
    __shared__ float sbuf[8];
    const int b = blockIdx.y, q = blockIdx.x;
    __nv_bfloat16* oh = g_ah + ((size_t)b * NHW + q) * NHW;
    __nv_bfloat16* ol = g_al + ((size_t)b * NHW + q) * NHW;
    const int tid = threadIdx.x;

    float v[16];
#pragma unroll
    for (int j = 0; j < 4; j++) {
        size_t off = (size_t)(tid + j * 256) * 4;
        uint2 hh = *(uint2*)&oh[off];
        uint2 ll = *(uint2*)&ol[off];
        float2 h0 = __bfloat1622float2(*(__nv_bfloat162*)&hh.x);
        float2 h1 = __bfloat1622float2(*(__nv_bfloat162*)&hh.y);
        float2 l0 = __bfloat1622float2(*(__nv_bfloat162*)&ll.x);
        float2 l1 = __bfloat1622float2(*(__nv_bfloat162*)&ll.y);
        v[j * 4 + 0] = h0.x + l0.x;
        v[j * 4 + 1] = h0.y + l0.y;
        v[j * 4 + 2] = h1.x + l1.x;
        v[j * 4 + 3] = h1.y + l1.y;
    }

    float m = v[0];
#pragma unroll
    for (int e = 1; e < 16; e++) m = fmaxf(m, v[e]);
#pragma unroll
    for (int o = 16; o > 0; o >>= 1) m = fmaxf(m, __shfl_xor_sync(0xffffffffu, m, o));
    if ((tid & 31) == 0) sbuf[tid >> 5] = m;
    __syncthreads();
    m = sbuf[0];
#pragma unroll
    for (int w = 1; w < 8; w++) m = fmaxf(m, sbuf[w]);
    __syncthreads();

    float s = 0.f;
#pragma unroll
    for (int e = 0; e < 16; e++) { v[e] = expf(v[e] - m); s += v[e]; }
#pragma unroll
    for (int o = 16; o > 0; o >>= 1) s += __shfl_xor_sync(0xffffffffu, s, o);
    if ((tid & 31) == 0) sbuf[tid >> 5] = s;
    __syncthreads();
    s = 0.f;
#pragma unroll
    for (int w = 0; w < 8; w++) s += sbuf[w];
    float inv = 1.f / s;

#pragma unroll
    for (int j = 0; j < 4; j++) {
        __nv_bfloat16 h4[4], l4[4];
#pragma unroll
        for (int e = 0; e < 4; e++) split_bf16(v[j * 4 + e] * inv, h4[e], l4[e]);
        size_t off = (size_t)(tid + j * 256) * 4;
        *(uint2*)&oh[off] = *(uint2*)h4;
        *(uint2*)&ol[off] = *(uint2*)l4;
    }
}

// ============================================================
// Kernel 4: out[b,c,q] = gamma * sum_k v[c,k] p[q,k] + beta * x_v[c,q]
// grid (32, B), block 256 (8 warps, 2x4). K=4096 in 128 chunks of 32,
// register-prefetched into a single 40KB static smem buffer.
// ============================================================
__global__ __launch_bounds__(256, 1) void out_tc_kernel(
    const float* __restrict__ xv, const float* __restrict__ gamma,
    const float* __restrict__ beta, float* __restrict__ out)
{
    __shared__ __align__(16) char st[4][T_BYTES];   // vh, vl, ah, al
    const int tid = threadIdx.x, wid = tid >> 5, lane = tid & 31;
    const int b = blockIdx.y, q0 = blockIdx.x << 7;

    const char* srcs[4] = {
        (const char*)(g_vh + (size_t)b * NC * NHW),
        (const char*)(g_vl + (size_t)b * NC * NHW),
        (const char*)(g_ah + ((size_t)b * NHW + q0) * NHW),
        (const char*)(g_al + ((size_t)b * NHW + q0) * NHW) };

    uint4 pf[4][2];
    auto fetch = [&](int kc) {
#pragma unroll
        for (int t = 0; t < 4; t++)
#pragma unroll
            for (int j = 0; j < 2; j++) {
                int idx = j * 256 + tid, r = idx >> 2, ch = idx & 3;
                pf[t][j] = *(const uint4*)(srcs[t] + (size_t)r * 8192 + kc * 64 + ch * 16);
            }
    };
    auto stos = [&]() {
#pragma unroll
        for (int t = 0; t < 4; t++)
#pragma unroll
            for (int j = 0; j < 2; j++) {
                int idx = j * 256 + tid, r = idx >> 2, ch = idx & 3;
                *(uint4*)(st[t] + r * T_ROWB + ch * 16) = pf[t][j];
            }
    };

    const int wm = wid & 1, wn = wid >> 1;
    const int lrA = lane & 15, lcA = lane >> 4;

    float acc[4][4][4];
#pragma unroll
    for (int am = 0; am < 4; am++)
#pragma unroll
        for (int an = 0; an < 4; an++)
#pragma unroll
            for (int f = 0; f < 4; f++) acc[am][an][f] = 0.f;

    const uint32_t tvh = smem_to_u32(st[0]), tvl = smem_to_u32(st[1]);
    const uint32_t tah = smem_to_u32(st[2]), tal = smem_to_u32(st[3]);

    fetch(0); stos();
    __syncthreads();

    for (int kc = 0; kc < 128; kc++) {
        if (kc < 127) fetch(kc + 1);
#pragma unroll
        for (int kk = 0; kk < 2; kk++) {
            int chl = kk * 2 + lcA;
            uint32_t ah[4][4], al[4][4];
#pragma unroll
            for (int am = 0; am < 4; am++) {
                uint32_t off = (uint32_t)((wm * 64 + am * 16 + lrA) * T_ROWB + chl * 16);
                ldsm_x4(ah[am], tvh + off);
                ldsm_x4(al[am], tvl + off);
            }
            uint32_t bh[4][2], bl[4][2];
#pragma unroll
            for (int pr = 0; pr < 2; pr++) {
                uint32_t off = (uint32_t)((wn * 32 + pr * 16 + lrA) * T_ROWB + chl * 16);
                uint32_t t[4];
                ldsm_x4(t, tah + off);
                bh[pr * 2][0] = t[0]; bh[pr * 2][1] = t[2];
                bh[pr * 2 + 1][0] = t[1]; bh[pr * 2 + 1][1] = t[3];
                ldsm_x4(t, tal + off);
                bl[pr * 2][0] = t[0]; bl[pr * 2][1] = t[2];
                bl[pr * 2 + 1][0] = t[1]; bl[pr * 2 + 1][1] = t[3];
            }
#pragma unroll
            for (int am = 0; am < 4; am++)
#pragma unroll
                for (int an = 0; an < 4; an++) {
                    mma16816(acc[am][an], ah[am], bh[an]);   // v_hi * p_hi
                    mma16816(acc[am][an], ah[am], bl[an]);   // v_hi * p_lo
                    mma16816(acc[am][an], al[am], bh[an]);   // v_lo * p_hi
                }
        }
        __syncthreads();
        if (kc < 127) { stos(); __syncthreads(); }
    }

    // epilogue: out = gamma*acc + beta*x_v
    const float gm = gamma[0];
    const float be = beta[0];
    const int g = lane >> 2, i2 = (lane & 3) << 1;
#pragma unroll
    for (int am = 0; am < 4; am++)
#pragma unroll
        for (int an = 0; an < 4; an++) {
            int crow = wm * 64 + am * 16 + g;
            int qcol = q0 + wn * 32 + an * 8 + i2;
            size_t off = ((size_t)(b * NC + crow)) * NHW + qcol;
            float2 x0 = *(const float2*)(xv + off);
            *(float2*)(out + off) = make_float2(gm * acc[am][an][0] + be * x0.x,
                                                gm * acc[am][an][1] + be * x0.y);
            size_t off8 = off + (size_t)8 * NHW;
            float2 x1 = *(const float2*)(xv + off8);
            *(float2*)(out + off8) = make_float2(gm * acc[am][an][2] + be * x1.x,
                                                 gm * acc[am][an][3] + be * x1.y);
        }
}

// ============================================================
extern "C" void kernel_launch(void* const* d_in, const int* in_sizes, int n_in,
                              void* d_out, int out_size)
{
    const float* x_q = (const float*)d_in[0];
    const float* x_k = (const float*)d_in[1];
    const float* x_v = (const float*)d_in[2];

    const float* q_w = (const float*)d_in[3];
    const float* q_b = (const float*)d_in[4];
    const float* q_s = (const float*)d_in[5];
    const float* q_bb = (const float*)d_in[6];
    const float* q_m = (const float*)d_in[7];
    const float* q_v = (const float*)d_in[8];

    const float* k_w = (const float*)d_in[9];
    const float* k_b = (const float*)d_in[10];
    const float* k_s = (const float*)d_in[11];
    const float* k_bb = (const float*)d_in[12];
    const float* k_m = (const float*)d_in[13];
    const float* k_v = (const float*)d_in[14];

    const float* v_w = (const float*)d_in[15];
    const float* v_b = (const float*)d_in[16];
    const float* v_s = (const float*)d_in[17];
    const float* v_bb = (const float*)d_in[18];
    const float* v_m = (const float*)d_in[19];
    const float* v_v = (const float*)d_in[20];

    const float* gamma = (const float*)d_in[21];
    const float* beta  = (const float*)d_in[22];

    dim3 bp(NHW / 64, NB);
    proj_kernel<<<bp, 256>>>(x_q, q_w, q_b, q_s, q_bb, q_m, q_v, 0);
    proj_kernel<<<bp, 256>>>(x_k, k_w, k_b, k_s, k_bb, k_m, k_v, 1);
    proj_kernel<<<bp, 256>>>(x_v, v_w, v_b, v_s, v_bb, v_m, v_v, 2);

    dim3 ge(NHW / 128, NHW / 128, NB);
    energy_tc_kernel<<<ge, 256>>>();

    dim3 gs(NHW, NB);
    softmax_kernel<<<gs, 256>>>();

    dim3 go(NHW / 128, NB);
    out_tc_kernel<<<go, 256>>>(x_v, gamma, beta, (float*)d_out);
}

// round 11
// speedup vs baseline: 2.7210x; 1.0021x over previous
#include <cuda_runtime.h>
#include <cuda_bf16.h>
#include <cstdint>
#include <math.h>

#define NB 4
#define NC 128
#define NHW 4096

// ---- scratch (no cudaMalloc; ~280 MiB total) ----
__device__ __nv_bfloat16 g_qh[(size_t)NB * NHW * NC];   // [b][hw][c]
__device__ __nv_bfloat16 g_ql[(size_t)NB * NHW * NC];
__device__ __nv_bfloat16 g_kh[(size_t)NB * NHW * NC];
__device__ __nv_bfloat16 g_kl[(size_t)NB * NHW * NC];
__device__ __nv_bfloat16 g_vh[(size_t)NB * NC * NHW];   // [b][c][hw]
__device__ __nv_bfloat16 g_vl[(size_t)NB * NC * NHW];
__device__ __nv_bfloat16 g_ah[(size_t)NB * NHW * NHW];  // [b][q][k] energies -> probs (hi)
__device__ __nv_bfloat16 g_al[(size_t)NB * NHW * NHW];  // (lo)

// ============================================================
// helpers (family-portable PTX only: ldmatrix sm_75+, mma.sync sm_80+)
// ============================================================
__device__ __forceinline__ uint32_t smem_to_u32(const void* p) {
    uint32_t a;
    asm("{ .reg .u64 t; cvta.to.shared.u64 t, %1; cvt.u32.u64 %0, t; }" : "=r"(a) : "l"(p));
    return a;
}
__device__ __forceinline__ void ldsm_x4(uint32_t* r, uint32_t addr) {
    asm volatile("ldmatrix.sync.aligned.m8n8.x4.shared.b16 {%0,%1,%2,%3}, [%4];"
                 : "=r"(r[0]), "=r"(r[1]), "=r"(r[2]), "=r"(r[3]) : "r"(addr));
}
__device__ __forceinline__ void mma16816(float* c, const uint32_t* a, const uint32_t* b) {
    asm volatile("mma.sync.aligned.m16n8k16.row.col.f32.bf16.bf16.f32 "
                 "{%0,%1,%2,%3}, {%4,%5,%6,%7}, {%8,%9}, {%0,%1,%2,%3};"
                 : "+f"(c[0]), "+f"(c[1]), "+f"(c[2]), "+f"(c[3])
                 : "r"(a[0]), "r"(a[1]), "r"(a[2]), "r"(a[3]), "r"(b[0]), "r"(b[1]));
}
__device__ __forceinline__ void split_bf16(float v, __nv_bfloat16& h, __nv_bfloat16& l) {
    h = __float2bfloat16_rn(v);
    l = __float2bfloat16_rn(v - __bfloat162float(h));
}
__device__ __forceinline__ uint32_t pack2(__nv_bfloat16 a, __nv_bfloat16 b) {
    __nv_bfloat162 t(a, b);
    return *(uint32_t*)&t;
}

// tile geometry: 128 rows x 32 bf16 per chunk, row padded 64B -> 80B.
// ldmatrix 16B-bank index = (5r + ch) mod 8 : distinct over any 8 rows.
#define T_ROWB 80
#define T_BYTES (128 * T_ROWB)   // 10240; 4 tiles = 40960 B static smem

// ============================================================
// Kernel 1: 1x1 conv + BN + ELU, writes bf16 hi/lo split.
//   which 0/1 (q/k): layout [b][hw][c]; which 2 (v): [b][c][hw]
// grid (HW/64, B), block 256
// ============================================================
__global__ __launch_bounds__(256, 2) void proj_kernel(
    const float* __restrict__ x, const float* __restrict__ w,
    const float* __restrict__ cb, const float* __restrict__ bns,
    const float* __restrict__ bnb, const float* __restrict__ bnm,
    const float* __restrict__ bnv, int which)
{
    __shared__ float xs[NC][64];
    __shared__ float ws[32][NC];

    __nv_bfloat16* dh = (which == 0) ? g_qh : (which == 1) ? g_kh : g_vh;
    __nv_bfloat16* dl = (which == 0) ? g_ql : (which == 1) ? g_kl : g_vl;

    const int b   = blockIdx.y;
    const int hw0 = blockIdx.x * 64;
    const int tid = threadIdx.x;
    const int tx  = tid & 15;
    const int ty  = tid >> 4;
    const float* xb = x + (size_t)b * NC * NHW;

    for (int i = tid; i < NC * 16; i += 256) {
        int c = i >> 4, j = (i & 15) << 2;
        *(float4*)&xs[c][j] = *(const float4*)&xb[(size_t)c * NHW + hw0 + j];
    }

    float acc[8][4];
#pragma unroll
    for (int i = 0; i < 8; i++)
#pragma unroll
        for (int j = 0; j < 4; j++) acc[i][j] = 0.f;

    for (int c0 = 0; c0 < NC; c0 += 32) {
        __syncthreads();
        for (int i = tid; i < 1024; i += 256) {
            int o = i >> 3, cf = (i & 7) << 2;
            float4 t = *(const float4*)&w[o * NC + c0 + cf];
            ws[cf + 0][o] = t.x; ws[cf + 1][o] = t.y;
            ws[cf + 2][o] = t.z; ws[cf + 3][o] = t.w;
        }
        __syncthreads();
#pragma unroll 4
        for (int cc = 0; cc < 32; cc++) {
            float wr[8];
            *(float4*)&wr[0] = *(float4*)&ws[cc][ty * 8];
            *(float4*)&wr[4] = *(float4*)&ws[cc][ty * 8 + 4];
            float4 xv = *(float4*)&xs[c0 + cc][tx * 4];
#pragma unroll
            for (int i = 0; i < 8; i++) {
                acc[i][0] += wr[i] * xv.x;
                acc[i][1] += wr[i] * xv.y;
                acc[i][2] += wr[i] * xv.z;
                acc[i][3] += wr[i] * xv.w;
            }
        }
    }

    float vout[8][4];
#pragma unroll
    for (int i = 0; i < 8; i++) {
        int o = ty * 8 + i;
        float inv = bns[o] * rsqrtf(bnv[o] + 1e-5f);
        float add = cb[o] * inv + bnb[o] - bnm[o] * inv;
#pragma unroll
        for (int j = 0; j < 4; j++) {
            float v = acc[i][j] * inv + add;
            vout[i][j] = v > 0.f ? v : expm1f(v);
        }
    }

    if (which < 2) {
#pragma unroll
        for (int j = 0; j < 4; j++) {
            int hw = hw0 + tx * 4 + j;
            __nv_bfloat16 h8[8], l8[8];
#pragma unroll
            for (int i = 0; i < 8; i++) split_bf16(vout[i][j], h8[i], l8[i]);
            size_t off = ((size_t)b * NHW + hw) * NC + ty * 8;
            *(uint4*)&dh[off] = *(uint4*)h8;
            *(uint4*)&dl[off] = *(uint4*)l8;
        }
    } else {
#pragma unroll
        for (int i = 0; i < 8; i++) {
            int o = ty * 8 + i;
            __nv_bfloat16 h4[4], l4[4];
#pragma unroll
            for (int j = 0; j < 4; j++) split_bf16(vout[i][j], h4[j], l4[j]);
            size_t off = ((size_t)(b * NC + o)) * NHW + hw0 + tx * 4;
            *(uint2*)&dh[off] = *(uint2*)h4;
            *(uint2*)&dl[off] = *(uint2*)l4;
        }
    }
}

// ============================================================
// Kernel 2: energy[b,qi,ki] = sum_c q.k  (bf16x3 mma.sync)
// grid (32,32,B), block 256 (8 warps, 2x4). K=128 in 4 chunks of 32.
// Writes energies as bf16 hi/lo into g_ah/g_al (softmax renormalizes in place).
// ============================================================
__global__ __launch_bounds__(256, 1) void energy_tc_kernel()
{
    __shared__ __align__(16) char st[4][T_BYTES];   // qh, ql, kh, kl
    const int tid = threadIdx.x, wid = tid >> 5, lane = tid & 31;
    const int b = blockIdx.z, q0 = blockIdx.y << 7, k0 = blockIdx.x << 7;

    const char* srcs[4] = {
        (const char*)(g_qh + ((size_t)b * NHW + q0) * NC),
        (const char*)(g_ql + ((size_t)b * NHW + q0) * NC),
        (const char*)(g_kh + ((size_t)b * NHW + k0) * NC),
        (const char*)(g_kl + ((size_t)b * NHW + k0) * NC) };

    uint4 pf[4][2];
    auto fetch = [&](int kc) {
#pragma unroll
        for (int t = 0; t < 4; t++)
#pragma unroll
            for (int j = 0; j < 2; j++) {
                int idx = j * 256 + tid, r = idx >> 2, ch = idx & 3;
                pf[t][j] = *(const uint4*)(srcs[t] + (size_t)r * 256 + kc * 64 + ch * 16);
            }
    };
    auto stos = [&]() {
#pragma unroll
        for (int t = 0; t < 4; t++)
#pragma unroll
            for (int j = 0; j < 2; j++) {
                int idx = j * 256 + tid, r = idx >> 2, ch = idx & 3;
                *(uint4*)(st[t] + r * T_ROWB + ch * 16) = pf[t][j];
            }
    };

    const int wm = wid & 1, wn = wid >> 1;
    const int lrA = lane & 15, lcA = lane >> 4;

    float acc[4][4][4];
#pragma unroll
    for (int am = 0; am < 4; am++)
#pragma unroll
        for (int an = 0; an < 4; an++)
#pragma unroll
            for (int f = 0; f < 4; f++) acc[am][an][f] = 0.f;

    const uint32_t tqh = smem_to_u32(st[0]), tql = smem_to_u32(st[1]);
    const uint32_t tkh = smem_to_u32(st[2]), tkl = smem_to_u32(st[3]);

    fetch(0); stos();
    __syncthreads();

    for (int kc = 0; kc < 4; kc++) {
        if (kc < 3) fetch(kc + 1);
#pragma unroll
        for (int kk = 0; kk < 2; kk++) {
            int chl = kk * 2 + lcA;
            uint32_t ah[4][4], al[4][4];
#pragma unroll
            for (int am = 0; am < 4; am++) {
                uint32_t off = (uint32_t)((wm * 64 + am * 16 + lrA) * T_ROWB + chl * 16);
                ldsm_x4(ah[am], tqh + off);
                ldsm_x4(al[am], tql + off);
            }
            uint32_t bh[4][2], bl[4][2];
#pragma unroll
            for (int pr = 0; pr < 2; pr++) {
                uint32_t off = (uint32_t)((wn * 32 + pr * 16 + lrA) * T_ROWB + chl * 16);
                uint32_t t[4];
                ldsm_x4(t, tkh + off);
                bh[pr * 2][0] = t[0]; bh[pr * 2][1] = t[2];
                bh[pr * 2 + 1][0] = t[1]; bh[pr * 2 + 1][1] = t[3];
                ldsm_x4(t, tkl + off);
                bl[pr * 2][0] = t[0]; bl[pr * 2][1] = t[2];
                bl[pr * 2 + 1][0] = t[1]; bl[pr * 2 + 1][1] = t[3];
            }
#pragma unroll
            for (int am = 0; am < 4; am++)
#pragma unroll
                for (int an = 0; an < 4; an++) {
                    mma16816(acc[am][an], ah[am], bh[an]);
                    mma16816(acc[am][an], ah[am], bl[an]);
                    mma16816(acc[am][an], al[am], bh[an]);
                }
        }
        __syncthreads();
        if (kc < 3) { stos(); __syncthreads(); }
    }

    // epilogue: split energies to bf16 hi/lo
    const int g = lane >> 2, i2 = (lane & 3) << 1;
#pragma unroll
    for (int am = 0; am < 4; am++)
#pragma unroll
        for (int an = 0; an < 4; an++) {
            int row = q0 + wm * 64 + am * 16 + g;
            int col = k0 + wn * 32 + an * 8 + i2;
            size_t off = ((size_t)b * NHW + row) * NHW + col;
            __nv_bfloat16 h0, l0, h1, l1;
            split_bf16(acc[am][an][0], h0, l0);
            split_bf16(acc[am][an][1], h1, l1);
            *(uint32_t*)&g_ah[off] = pack2(h0, h1);
            *(uint32_t*)&g_al[off] = pack2(l0, l1);
            size_t off8 = off + (size_t)8 * NHW;
            split_bf16(acc[am][an][2], h0, l0);
            split_bf16(acc[am][an][3], h1, l1);
            *(uint32_t*)&g_ah[off8] = pack2(h0, h1);
            *(uint32_t*)&g_al[off8] = pack2(l0, l1);
        }
}

// ============================================================
// Kernel 3: softmax in place on (g_ah + g_al). grid (HW, B), 256 thr.
// __expf: MUFU.EX2 fast path (rel err 2^-21, fine for probabilities).
// ============================================================
__global__ __launch_bounds__(256) void softmax_kernel()
{
    __shared__ float sbuf[8];
    const int b = blockIdx.y, q = blockIdx.x;
    __nv_bfloat16* oh = g_ah + ((size_t)b * NHW + q) * NHW;
    __nv_bfloat16* ol = g_al + ((size_t)b * NHW + q) * NHW;
    const int tid = threadIdx.x;

    float v[16];
#pragma unroll
    for (int j = 0; j < 4; j++) {
        size_t off = (size_t)(tid + j * 256) * 4;
        uint2 hh = *(uint2*)&oh[off];
        uint2 ll = *(uint2*)&ol[off];
        float2 h0 = __bfloat1622float2(*(__nv_bfloat162*)&hh.x);
        float2 h1 = __bfloat1622float2(*(__nv_bfloat162*)&hh.y);
        float2 l0 = __bfloat1622float2(*(__nv_bfloat162*)&ll.x);
        float2 l1 = __bfloat1622float2(*(__nv_bfloat162*)&ll.y);
        v[j * 4 + 0] = h0.x + l0.x;
        v[j * 4 + 1] = h0.y + l0.y;
        v[j * 4 + 2] = h1.x + l1.x;
        v[j * 4 + 3] = h1.y + l1.y;
    }

    float m = v[0];
#pragma unroll
    for (int e = 1; e < 16; e++) m = fmaxf(m, v[e]);
#pragma unroll
    for (int o = 16; o > 0; o >>= 1) m = fmaxf(m, __shfl_xor_sync(0xffffffffu, m, o));
    if ((tid & 31) == 0) sbuf[tid >> 5] = m;
    __syncthreads();
    m = sbuf[0];
#pragma unroll
    for (int w = 1; w < 8; w++) m = fmaxf(m, sbuf[w]);
    __syncthreads();

    float s = 0.f;
#pragma unroll
    for (int e = 0; e < 16; e++) { v[e] = __expf(v[e] - m); s += v[e]; }
#pragma unroll
    for (int o = 16; o > 0; o >>= 1) s += __shfl_xor_sync(0xffffffffu, s, o);
    if ((tid & 31) == 0) sbuf[tid >> 5] = s;
    __syncthreads();
    s = 0.f;
#pragma unroll
    for (int w = 0; w < 8; w++) s += sbuf[w];
    float inv = 1.f / s;

#pragma unroll
    for (int j = 0; j < 4; j++) {
        __nv_bfloat16 h4[4], l4[4];
#pragma unroll
        for (int e = 0; e < 4; e++) split_bf16(v[j * 4 + e] * inv, h4[e], l4[e]);
        size_t off = (size_t)(tid + j * 256) * 4;
        *(uint2*)&oh[off] = *(uint2*)h4;
        *(uint2*)&ol[off] = *(uint2*)l4;
    }
}

// ============================================================
// Kernel 4: out[b,c,q] = gamma * sum_k v[c,k] p[q,k] + beta * x_v[c,q]
// grid (32, B), block 256 (8 warps, 2x4). K=4096 in 128 chunks of 32,
// register-prefetched into a single 40KB static smem buffer.
// ============================================================
__global__ __launch_bounds__(256, 1) void out_tc_kernel(
    const float* __restrict__ xv, const float* __restrict__ gamma,
    const float* __restrict__ beta, float* __restrict__ out)
{
    __shared__ __align__(16) char st[4][T_BYTES];   // vh, vl, ah, al
    const int tid = threadIdx.x, wid = tid >> 5, lane = tid & 31;
    const int b = blockIdx.y, q0 = blockIdx.x << 7;

    const char* srcs[4] = {
        (const char*)(g_vh + (size_t)b * NC * NHW),
        (const char*)(g_vl + (size_t)b * NC * NHW),
        (const char*)(g_ah + ((size_t)b * NHW + q0) * NHW),
        (const char*)(g_al + ((size_t)b * NHW + q0) * NHW) };

    uint4 pf[4][2];
    auto fetch = [&](int kc) {
#pragma unroll
        for (int t = 0; t < 4; t++)
#pragma unroll
            for (int j = 0; j < 2; j++) {
                int idx = j * 256 + tid, r = idx >> 2, ch = idx & 3;
                pf[t][j] = *(const uint4*)(srcs[t] + (size_t)r * 8192 + kc * 64 + ch * 16);
            }
    };
    auto stos = [&]() {
#pragma unroll
        for (int t = 0; t < 4; t++)
#pragma unroll
            for (int j = 0; j < 2; j++) {
                int idx = j * 256 + tid, r = idx >> 2, ch = idx & 3;
                *(uint4*)(st[t] + r * T_ROWB + ch * 16) = pf[t][j];
            }
    };

    const int wm = wid & 1, wn = wid >> 1;
    const int lrA = lane & 15, lcA = lane >> 4;

    float acc[4][4][4];
#pragma unroll
    for (int am = 0; am < 4; am++)
#pragma unroll
        for (int an = 0; an < 4; an++)
#pragma unroll
            for (int f = 0; f < 4; f++) acc[am][an][f] = 0.f;

    const uint32_t tvh = smem_to_u32(st[0]), tvl = smem_to_u32(st[1]);
    const uint32_t tah = smem_to_u32(st[2]), tal = smem_to_u32(st[3]);

    fetch(0); stos();
    __syncthreads();

    for (int kc = 0; kc < 128; kc++) {
        if (kc < 127) fetch(kc + 1);
#pragma unroll
        for (int kk = 0; kk < 2; kk++) {
            int chl = kk * 2 + lcA;
            uint32_t ah[4][4], al[4][4];
#pragma unroll
            for (int am = 0; am < 4; am++) {
                uint32_t off = (uint32_t)((wm * 64 + am * 16 + lrA) * T_ROWB + chl * 16);
                ldsm_x4(ah[am], tvh + off);
                ldsm_x4(al[am], tvl + off);
            }
            uint32_t bh[4][2], bl[4][2];
#pragma unroll
            for (int pr = 0; pr < 2; pr++) {
                uint32_t off = (uint32_t)((wn * 32 + pr * 16 + lrA) * T_ROWB + chl * 16);
                uint32_t t[4];
                ldsm_x4(t, tah + off);
                bh[pr * 2][0] = t[0]; bh[pr * 2][1] = t[2];
                bh[pr * 2 + 1][0] = t[1]; bh[pr * 2 + 1][1] = t[3];
                ldsm_x4(t, tal + off);
                bl[pr * 2][0] = t[0]; bl[pr * 2][1] = t[2];
                bl[pr * 2 + 1][0] = t[1]; bl[pr * 2 + 1][1] = t[3];
            }
#pragma unroll
            for (int am = 0; am < 4; am++)
#pragma unroll
                for (int an = 0; an < 4; an++) {
                    mma16816(acc[am][an], ah[am], bh[an]);   // v_hi * p_hi
                    mma16816(acc[am][an], ah[am], bl[an]);   // v_hi * p_lo
                    mma16816(acc[am][an], al[am], bh[an]);   // v_lo * p_hi
                }
        }
        __syncthreads();
        if (kc < 127) { stos(); __syncthreads(); }
    }

    // epilogue: out = gamma*acc + beta*x_v
    const float gm = gamma[0];
    const float be = beta[0];
    const int g = lane >> 2, i2 = (lane & 3) << 1;
#pragma unroll
    for (int am = 0; am < 4; am++)
#pragma unroll
        for (int an = 0; an < 4; an++) {
            int crow = wm * 64 + am * 16 + g;
            int qcol = q0 + wn * 32 + an * 8 + i2;
            size_t off = ((size_t)(b * NC + crow)) * NHW + qcol;
            float2 x0 = *(const float2*)(xv + off);
            *(float2*)(out + off) = make_float2(gm * acc[am][an][0] + be * x0.x,
                                                gm * acc[am][an][1] + be * x0.y);
            size_t off8 = off + (size_t)8 * NHW;
            float2 x1 = *(const float2*)(xv + off8);
            *(float2*)(out + off8) = make_float2(gm * acc[am][an][2] + be * x1.x,
                                                 gm * acc[am][an][3] + be * x1.y);
        }
}

// ============================================================
extern "C" void kernel_launch(void* const* d_in, const int* in_sizes, int n_in,
                              void* d_out, int out_size)
{
    const float* x_q = (const float*)d_in[0];
    const float* x_k = (const float*)d_in[1];
    const float* x_v = (const float*)d_in[2];

    const float* q_w = (const float*)d_in[3];
    const float* q_b = (const float*)d_in[4];
    const float* q_s = (const float*)d_in[5];
    const float* q_bb = (const float*)d_in[6];
    const float* q_m = (const float*)d_in[7];
    const float* q_v = (const float*)d_in[8];

    const float* k_w = (const float*)d_in[9];
    const float* k_b = (const float*)d_in[10];
    const float* k_s = (const float*)d_in[11];
    const float* k_bb = (const float*)d_in[12];
    const float* k_m = (const float*)d_in[13];
    const float* k_v = (const float*)d_in[14];

    const float* v_w = (const float*)d_in[15];
    const float* v_b = (const float*)d_in[16];
    const float* v_s = (const float*)d_in[17];
    const float* v_bb = (const float*)d_in[18];
    const float* v_m = (const float*)d_in[19];
    const float* v_v = (const float*)d_in[20];

    const float* gamma = (const float*)d_in[21];
    const float* beta  = (const float*)d_in[22];

    dim3 bp(NHW / 64, NB);
    proj_kernel<<<bp, 256>>>(x_q, q_w, q_b, q_s, q_bb, q_m, q_v, 0);
    proj_kernel<<<bp, 256>>>(x_k, k_w, k_b, k_s, k_bb, k_m, k_v, 1);
    proj_kernel<<<bp, 256>>>(x_v, v_w, v_b, v_s, v_bb, v_m, v_v, 2);

    dim3 ge(NHW / 128, NHW / 128, NB);
    energy_tc_kernel<<<ge, 256>>>();

    dim3 gs(NHW, NB);
    softmax_kernel<<<gs, 256>>>();

    dim3 go(NHW / 128, NB);
    out_tc_kernel<<<go, 256>>>(x_v, gamma, beta, (float*)d_out);
}